// round 1
// baseline (speedup 1.0000x reference)
#include <cuda_runtime.h>
#include <math.h>

// ---------------------------------------------------------------------------
// DonutSwinLayer: B=16, H=W=64, C=512, NH=16, HD=32, WS=8, N=64, SS=4, MLP=2048
// Token count = 16*64*64 = 65536. All fp32.
// ---------------------------------------------------------------------------

#define NTOK   65536
#define CDIM   512
#define NHEADS 16
#define HDIM   32
#define WSZ    8
#define NWTOK  64      // tokens per window
#define SSH    4       // shift
#define MLPD   2048

// Scratch: xw, q, k, v, ctx, po, h, y  (8 x NTOK*C) + mlp (NTOK*MLPD = 4x)
__device__ float g_scratch[(size_t)12 * NTOK * CDIM];

// ---------------------------------------------------------------------------
// Block reduction (128 threads) for sum and sum-of-squares
// ---------------------------------------------------------------------------
__device__ __forceinline__ void block_reduce_2(float& s, float& s2) {
    #pragma unroll
    for (int o = 16; o > 0; o >>= 1) {
        s  += __shfl_down_sync(0xffffffffu, s,  o);
        s2 += __shfl_down_sync(0xffffffffu, s2, o);
    }
    __shared__ float sh[8];
    int w = threadIdx.x >> 5, l = threadIdx.x & 31;
    if (l == 0) { sh[w] = s; sh[4 + w] = s2; }
    __syncthreads();
    s  = sh[0] + sh[1] + sh[2] + sh[3];
    s2 = sh[4] + sh[5] + sh[6] + sh[7];
}

// ---------------------------------------------------------------------------
// LN1 fused with cyclic shift (-SS,-SS) + window partition gather.
// One block per WINDOW row (destination). 128 threads, 4 elems each.
// window row wr -> (b, wi, n); shifted coords (hs,ws); source token
// at ((hs+SS)%64, (ws+SS)%64).
// ---------------------------------------------------------------------------
__global__ void ln1_gather_kernel(const float* __restrict__ hid,
                                  const float* __restrict__ g,
                                  const float* __restrict__ b,
                                  float* __restrict__ xw) {
    int wr = blockIdx.x;
    int t  = threadIdx.x;
    int b_  = wr >> 12;
    int rem = wr & 4095;
    int wi  = rem >> 6;
    int n   = rem & 63;
    int wh = wi >> 3, ww = wi & 7;
    int i  = n  >> 3, j  = n  & 7;
    int sh_ = ((wh * 8 + i) + SSH) & 63;
    int sw_ = ((ww * 8 + j) + SSH) & 63;
    const float* src = hid + ((size_t)b_ * 4096 + sh_ * 64 + sw_) * CDIM;

    float v[4];
    float s = 0.f, s2 = 0.f;
    #pragma unroll
    for (int u = 0; u < 4; u++) {
        v[u] = src[t + u * 128];
        s += v[u]; s2 += v[u] * v[u];
    }
    block_reduce_2(s, s2);
    float mu  = s * (1.f / CDIM);
    float var = s2 * (1.f / CDIM) - mu * mu;
    float inv = rsqrtf(var + 1e-5f);

    float* dst = xw + (size_t)wr * CDIM;
    #pragma unroll
    for (int u = 0; u < 4; u++) {
        int c = t + u * 128;
        dst[c] = (v[u] - mu) * inv * g[c] + b[c];
    }
}

// ---------------------------------------------------------------------------
// Plain LayerNorm (one block per token row)
// ---------------------------------------------------------------------------
__global__ void ln_plain_kernel(const float* __restrict__ x,
                                const float* __restrict__ g,
                                const float* __restrict__ b,
                                float* __restrict__ y) {
    int r = blockIdx.x;
    int t = threadIdx.x;
    const float* src = x + (size_t)r * CDIM;
    float v[4];
    float s = 0.f, s2 = 0.f;
    #pragma unroll
    for (int u = 0; u < 4; u++) {
        v[u] = src[t + u * 128];
        s += v[u]; s2 += v[u] * v[u];
    }
    block_reduce_2(s, s2);
    float mu  = s * (1.f / CDIM);
    float var = s2 * (1.f / CDIM) - mu * mu;
    float inv = rsqrtf(var + 1e-5f);
    float* dst = y + (size_t)r * CDIM;
    #pragma unroll
    for (int u = 0; u < 4; u++) {
        int c = t + u * 128;
        dst[c] = (v[u] - mu) * inv * g[c] + b[c];
    }
}

// ---------------------------------------------------------------------------
// Residual scatter: h[global token] = hidden[global token] + po[window row]
// One block per window row, 128 threads x 4.
// ---------------------------------------------------------------------------
__global__ void resid_scatter_kernel(const float* __restrict__ hid,
                                     const float* __restrict__ po,
                                     float* __restrict__ h) {
    int wr = blockIdx.x;
    int t  = threadIdx.x;
    int b_  = wr >> 12;
    int rem = wr & 4095;
    int wi  = rem >> 6;
    int n   = rem & 63;
    int wh = wi >> 3, ww = wi & 7;
    int i  = n  >> 3, j  = n  & 7;
    int sh_ = ((wh * 8 + i) + SSH) & 63;
    int sw_ = ((ww * 8 + j) + SSH) & 63;
    size_t dst  = ((size_t)b_ * 4096 + sh_ * 64 + sw_) * CDIM;
    size_t srcr = (size_t)wr * CDIM;
    #pragma unroll
    for (int u = 0; u < 4; u++) {
        int c = t + u * 128;
        h[dst + c] = hid[dst + c] + po[srcr + c];
    }
}

// ---------------------------------------------------------------------------
// Tiled fp32 GEMM: C[m][n] = sum_k A[m][k] * W[n][k] + bias[n]
// A: M x K row-major (M covered by grid.y*128), W: N x K row-major.
// BM=BN=128, BK=8, 256 threads, 8x8 per-thread micro-tile.
// mode: 0 plain, 1 gelu(exact), 2 add residual (add[m][n])
// ---------------------------------------------------------------------------
__global__ __launch_bounds__(256)
void gemm128_kernel(const float* __restrict__ A, const float* __restrict__ W,
                    const float* __restrict__ bias, float* __restrict__ C,
                    int N, int K, int mode, const float* __restrict__ add) {
    __shared__ float As[8][128];
    __shared__ float Bs[8][128];
    const int tid = threadIdx.x;
    const int bm = blockIdx.y * 128;
    const int bn = blockIdx.x * 128;
    const int tx = tid & 15;
    const int ty = tid >> 4;
    const int lr = tid >> 1;
    const int lc = (tid & 1) * 4;

    const float* Ap = A + (size_t)(bm + lr) * K + lc;
    const float* Wp = W + (size_t)(bn + lr) * K + lc;

    float acc[8][8];
    #pragma unroll
    for (int i = 0; i < 8; i++)
        #pragma unroll
        for (int j = 0; j < 8; j++) acc[i][j] = 0.f;

    for (int k0 = 0; k0 < K; k0 += 8) {
        float4 a4 = *(const float4*)(Ap + k0);
        float4 b4 = *(const float4*)(Wp + k0);
        As[lc + 0][lr] = a4.x; As[lc + 1][lr] = a4.y;
        As[lc + 2][lr] = a4.z; As[lc + 3][lr] = a4.w;
        Bs[lc + 0][lr] = b4.x; Bs[lc + 1][lr] = b4.y;
        Bs[lc + 2][lr] = b4.z; Bs[lc + 3][lr] = b4.w;
        __syncthreads();
        #pragma unroll
        for (int kk = 0; kk < 8; kk++) {
            float ar[8], br[8];
            *(float4*)(ar)     = *(const float4*)&As[kk][ty * 8];
            *(float4*)(ar + 4) = *(const float4*)&As[kk][ty * 8 + 4];
            *(float4*)(br)     = *(const float4*)&Bs[kk][tx * 8];
            *(float4*)(br + 4) = *(const float4*)&Bs[kk][tx * 8 + 4];
            #pragma unroll
            for (int i = 0; i < 8; i++)
                #pragma unroll
                for (int j = 0; j < 8; j++)
                    acc[i][j] += ar[i] * br[j];
        }
        __syncthreads();
    }

    #pragma unroll
    for (int ii = 0; ii < 8; ii++) {
        int row = bm + ty * 8 + ii;
        float* crow = C + (size_t)row * N + bn + tx * 8;
        const float* arow = (mode == 2) ? (add + (size_t)row * N + bn + tx * 8) : nullptr;
        #pragma unroll
        for (int jj = 0; jj < 8; jj++) {
            float vv = acc[ii][jj] + bias[bn + tx * 8 + jj];
            if (mode == 1) {
                vv = 0.5f * vv * (1.f + erff(vv * 0.70710678118654752f));
            } else if (mode == 2) {
                vv += arow[jj];
            }
            crow[jj] = vv;
        }
    }
}

// ---------------------------------------------------------------------------
// Windowed attention: one block per (window, head). 64 threads (1 per query).
// Relative position bias and shift mask computed analytically.
// ---------------------------------------------------------------------------
__global__ __launch_bounds__(64)
void attn_kernel(const float* __restrict__ q, const float* __restrict__ k,
                 const float* __restrict__ v, const float* __restrict__ btab,
                 float* __restrict__ ctx) {
    __shared__ float qs[64][32];
    __shared__ float ks[64][32];
    __shared__ float vs[64][32];
    __shared__ float sc[64][65];
    __shared__ int   rid[64];

    int win  = blockIdx.x;     // 0..1023
    int head = blockIdx.y;     // 0..15
    int n    = threadIdx.x;    // 0..63 (query index)

    int wi = win & 63;
    int wh = wi >> 3, ww = wi & 7;
    int i  = n  >> 3, j  = n  & 7;

    // region id on the SHIFTED image coordinates (for the attention mask)
    int hs = wh * 8 + i, wc = ww * 8 + j;
    int rh = (hs < 56) ? 0 : ((hs < 60) ? 1 : 2);
    int rw = (wc < 56) ? 0 : ((wc < 60) ? 1 : 2);
    rid[n] = rh * 3 + rw;

    size_t base = ((size_t)win * 64) * CDIM + head * HDIM;
    const float4* q4 = (const float4*)(q + base + (size_t)n * CDIM);
    const float4* k4 = (const float4*)(k + base + (size_t)n * CDIM);
    const float4* v4 = (const float4*)(v + base + (size_t)n * CDIM);
    #pragma unroll
    for (int u = 0; u < 8; u++) {
        ((float4*)qs[n])[u] = q4[u];
        ((float4*)ks[n])[u] = k4[u];
        ((float4*)vs[n])[u] = v4[u];
    }
    __syncthreads();

    float qr[32];
    #pragma unroll
    for (int d = 0; d < 32; d++) qr[d] = qs[n][d];

    const float scale = 0.17677669529663687f;  // 1/sqrt(32)
    int myrid = rid[n];

    for (int m = 0; m < 64; m++) {
        float acc = 0.f;
        #pragma unroll
        for (int d = 0; d < 32; d++) acc += qr[d] * ks[m][d];
        int hk = m >> 3, wk = m & 7;
        int bidx = (i - hk + 7) * 15 + (j - wk + 7);
        float bv = btab[bidx * NHEADS + head];
        float msk = (rid[m] == myrid) ? 0.f : -100.f;
        sc[n][m] = acc * scale + bv + msk;
    }

    // softmax over own row (no cross-thread deps)
    float mx = -1e30f;
    for (int m = 0; m < 64; m++) mx = fmaxf(mx, sc[n][m]);
    float sum = 0.f;
    for (int m = 0; m < 64; m++) {
        float e = expf(sc[n][m] - mx);
        sc[n][m] = e;
        sum += e;
    }
    float accv[32];
    #pragma unroll
    for (int d = 0; d < 32; d++) accv[d] = 0.f;
    for (int m = 0; m < 64; m++) {
        float p = sc[n][m];
        #pragma unroll
        for (int d = 0; d < 32; d++) accv[d] += p * vs[m][d];
    }
    float inv = 1.f / sum;
    float* o = ctx + base + (size_t)n * CDIM;
    #pragma unroll
    for (int d = 0; d < 32; d++) o[d] = accv[d] * inv;
}

// ---------------------------------------------------------------------------
// launch
// ---------------------------------------------------------------------------
extern "C" void kernel_launch(void* const* d_in, const int* in_sizes, int n_in,
                              void* d_out, int out_size) {
    const float* hid    = (const float*)d_in[0];
    const float* q_w    = (const float*)d_in[1];
    const float* q_b    = (const float*)d_in[2];
    const float* k_w    = (const float*)d_in[3];
    const float* k_b    = (const float*)d_in[4];
    const float* v_w    = (const float*)d_in[5];
    const float* v_b    = (const float*)d_in[6];
    const float* proj_w = (const float*)d_in[7];
    const float* proj_b = (const float*)d_in[8];
    const float* relb   = (const float*)d_in[9];
    const float* ln1w   = (const float*)d_in[10];
    const float* ln1b   = (const float*)d_in[11];
    const float* ln2w   = (const float*)d_in[12];
    const float* ln2b   = (const float*)d_in[13];
    const float* fc1w   = (const float*)d_in[14];
    const float* fc1b   = (const float*)d_in[15];
    const float* fc2w   = (const float*)d_in[16];
    const float* fc2b   = (const float*)d_in[17];

    float* base = nullptr;
    cudaGetSymbolAddress((void**)&base, g_scratch);
    const size_t TC = (size_t)NTOK * CDIM;
    float* xw  = base + 0 * TC;
    float* qb  = base + 1 * TC;
    float* kb  = base + 2 * TC;
    float* vb  = base + 3 * TC;
    float* cx  = base + 4 * TC;
    float* po  = base + 5 * TC;
    float* hb  = base + 6 * TC;
    float* yb  = base + 7 * TC;
    float* mlp = base + 8 * TC;   // 4*TC

    float* out = (float*)d_out;

    // 1. LN1 + shift + window partition
    ln1_gather_kernel<<<NTOK, 128>>>(hid, ln1w, ln1b, xw);

    // 2. QKV projections
    dim3 gC(CDIM / 128, NTOK / 128);
    gemm128_kernel<<<gC, 256>>>(xw, q_w, q_b, qb, CDIM, CDIM, 0, nullptr);
    gemm128_kernel<<<gC, 256>>>(xw, k_w, k_b, kb, CDIM, CDIM, 0, nullptr);
    gemm128_kernel<<<gC, 256>>>(xw, v_w, v_b, vb, CDIM, CDIM, 0, nullptr);

    // 3. windowed attention
    attn_kernel<<<dim3(1024, NHEADS), 64>>>(qb, kb, vb, relb, cx);

    // 4. output projection (window layout)
    gemm128_kernel<<<gC, 256>>>(cx, proj_w, proj_b, po, CDIM, CDIM, 0, nullptr);

    // 5. window reverse + unshift + residual
    resid_scatter_kernel<<<NTOK, 128>>>(hid, po, hb);

    // 6. LN2
    ln_plain_kernel<<<NTOK, 128>>>(hb, ln2w, ln2b, yb);

    // 7. fc1 + exact GELU
    gemm128_kernel<<<dim3(MLPD / 128, NTOK / 128), 256>>>(yb, fc1w, fc1b, mlp,
                                                          MLPD, CDIM, 1, nullptr);

    // 8. fc2 + residual -> output
    gemm128_kernel<<<gC, 256>>>(mlp, fc2w, fc2b, out, CDIM, MLPD, 2, hb);
}

// round 2
// speedup vs baseline: 3.0587x; 3.0587x over previous
#include <cuda_runtime.h>
#include <math.h>
#include <stdint.h>

// ---------------------------------------------------------------------------
// DonutSwinLayer: B=16, H=W=64, C=512, NH=16, HD=32, WS=8, N=64, SS=4, MLP=2048
// Round 2: TF32 tensor-core GEMMs (mma.sync m16n8k8), tf32 rounding at producers.
// ---------------------------------------------------------------------------

#define NTOK   65536
#define CDIM   512
#define NHEADS 16
#define HDIM   32
#define SSH    4
#define MLPD   2048

#define BM 128
#define BN 128
#define BK 32
#define KST 36   // BK + 4 pad (keeps 16B alignment: 36 floats = 144B = 9*16B)

// 13 x NTOK*CDIM floats of scratch (last region holds tf32-rounded weights)
__device__ float g_scratch[(size_t)13 * NTOK * CDIM];

__device__ __forceinline__ float to_tf32(float x) {
    uint32_t u;
    asm("cvt.rna.tf32.f32 %0, %1;" : "=r"(u) : "f"(x));
    return __uint_as_float(u);
}

__device__ __forceinline__ void cp_async16(uint32_t s, const float* g) {
    asm volatile("cp.async.cg.shared.global [%0], [%1], 16;" :: "r"(s), "l"(g));
}
__device__ __forceinline__ void cp_commit() {
    asm volatile("cp.async.commit_group;");
}
template<int N_> __device__ __forceinline__ void cp_wait() {
    asm volatile("cp.async.wait_group %0;" :: "n"(N_));
}

// ---------------------------------------------------------------------------
// Weight tf32-round prepass
// ---------------------------------------------------------------------------
__global__ void round_tf32_kernel(const float* __restrict__ src,
                                  float* __restrict__ dst, int n) {
    int i = blockIdx.x * blockDim.x + threadIdx.x;
    if (i < n) dst[i] = to_tf32(src[i]);
}

// ---------------------------------------------------------------------------
// Block reduction (128 threads) for sum and sum-of-squares
// ---------------------------------------------------------------------------
__device__ __forceinline__ void block_reduce_2(float& s, float& s2) {
    #pragma unroll
    for (int o = 16; o > 0; o >>= 1) {
        s  += __shfl_down_sync(0xffffffffu, s,  o);
        s2 += __shfl_down_sync(0xffffffffu, s2, o);
    }
    __shared__ float sh[8];
    int w = threadIdx.x >> 5, l = threadIdx.x & 31;
    if (l == 0) { sh[w] = s; sh[4 + w] = s2; }
    __syncthreads();
    s  = sh[0] + sh[1] + sh[2] + sh[3];
    s2 = sh[4] + sh[5] + sh[6] + sh[7];
}

// ---------------------------------------------------------------------------
// LN1 fused with cyclic shift + window partition (output tf32-rounded: feeds QKV)
// ---------------------------------------------------------------------------
__global__ void ln1_gather_kernel(const float* __restrict__ hid,
                                  const float* __restrict__ g,
                                  const float* __restrict__ b,
                                  float* __restrict__ xw) {
    int wr = blockIdx.x;
    int t  = threadIdx.x;
    int b_  = wr >> 12;
    int rem = wr & 4095;
    int wi  = rem >> 6;
    int n   = rem & 63;
    int wh = wi >> 3, ww = wi & 7;
    int i  = n  >> 3, j  = n  & 7;
    int sh_ = ((wh * 8 + i) + SSH) & 63;
    int sw_ = ((ww * 8 + j) + SSH) & 63;
    const float* src = hid + ((size_t)b_ * 4096 + sh_ * 64 + sw_) * CDIM;

    float v[4];
    float s = 0.f, s2 = 0.f;
    #pragma unroll
    for (int u = 0; u < 4; u++) {
        v[u] = src[t + u * 128];
        s += v[u]; s2 += v[u] * v[u];
    }
    block_reduce_2(s, s2);
    float mu  = s * (1.f / CDIM);
    float var = s2 * (1.f / CDIM) - mu * mu;
    float inv = rsqrtf(var + 1e-5f);

    float* dst = xw + (size_t)wr * CDIM;
    #pragma unroll
    for (int u = 0; u < 4; u++) {
        int c = t + u * 128;
        dst[c] = to_tf32((v[u] - mu) * inv * g[c] + b[c]);
    }
}

// ---------------------------------------------------------------------------
// Plain LayerNorm (output tf32-rounded: feeds fc1)
// ---------------------------------------------------------------------------
__global__ void ln_plain_kernel(const float* __restrict__ x,
                                const float* __restrict__ g,
                                const float* __restrict__ b,
                                float* __restrict__ y) {
    int r = blockIdx.x;
    int t = threadIdx.x;
    const float* src = x + (size_t)r * CDIM;
    float v[4];
    float s = 0.f, s2 = 0.f;
    #pragma unroll
    for (int u = 0; u < 4; u++) {
        v[u] = src[t + u * 128];
        s += v[u]; s2 += v[u] * v[u];
    }
    block_reduce_2(s, s2);
    float mu  = s * (1.f / CDIM);
    float var = s2 * (1.f / CDIM) - mu * mu;
    float inv = rsqrtf(var + 1e-5f);
    float* dst = y + (size_t)r * CDIM;
    #pragma unroll
    for (int u = 0; u < 4; u++) {
        int c = t + u * 128;
        dst[c] = to_tf32((v[u] - mu) * inv * g[c] + b[c]);
    }
}

// ---------------------------------------------------------------------------
// Residual scatter: h[global token] = hidden + po[window row]
// ---------------------------------------------------------------------------
__global__ void resid_scatter_kernel(const float* __restrict__ hid,
                                     const float* __restrict__ po,
                                     float* __restrict__ h) {
    int wr = blockIdx.x;
    int t  = threadIdx.x;
    int b_  = wr >> 12;
    int rem = wr & 4095;
    int wi  = rem >> 6;
    int n   = rem & 63;
    int wh = wi >> 3, ww = wi & 7;
    int i  = n  >> 3, j  = n  & 7;
    int sh_ = ((wh * 8 + i) + SSH) & 63;
    int sw_ = ((ww * 8 + j) + SSH) & 63;
    size_t dst  = ((size_t)b_ * 4096 + sh_ * 64 + sw_) * CDIM;
    size_t srcr = (size_t)wr * CDIM;
    #pragma unroll
    for (int u = 0; u < 4; u++) {
        int c = t + u * 128;
        h[dst + c] = hid[dst + c] + po[srcr + c];
    }
}

// ---------------------------------------------------------------------------
// TF32 tensor-core GEMM: C[m][n] = sum_k A[m][k]*W[n][k] + bias[n]
// BM=BN=128, BK=32, 256 threads (8 warps: 4 in M x 2 in N, warp tile 32x64).
// Double-buffered cp.async. mode: 0 plain, 1 gelu->tf32, 2 +residual.
// Inputs must already be tf32-rounded.
// ---------------------------------------------------------------------------
__global__ __launch_bounds__(256)
void gemm_tf32_kernel(const float* __restrict__ A, const float* __restrict__ W,
                      const float* __restrict__ bias, float* __restrict__ C,
                      int N, int K, int mode, const float* __restrict__ add) {
    extern __shared__ float sm[];
    float* As = sm;                         // [2][BM][KST]
    float* Bs = sm + 2 * BM * KST;          // [2][BN][KST]

    const int tid  = threadIdx.x;
    const int bm   = blockIdx.y * BM;
    const int bn   = blockIdx.x * BN;
    const int warp = tid >> 5;
    const int lane = tid & 31;
    const int wm   = (warp & 3) * 32;
    const int wn   = (warp >> 2) * 64;
    const int lr   = lane >> 2;   // 0..7
    const int lc   = lane & 3;    // 0..3

    uint32_t asmem = (uint32_t)__cvta_generic_to_shared(As);
    uint32_t bsmem = (uint32_t)__cvta_generic_to_shared(Bs);

    // loader: 1024 16B-chunks per tile, 4 per thread
    const int ldrow = tid >> 1;            // not used; chunk scheme below
    (void)ldrow;

    float acc[2][8][4];
    #pragma unroll
    for (int mt = 0; mt < 2; mt++)
        #pragma unroll
        for (int nt = 0; nt < 8; nt++)
            #pragma unroll
            for (int r = 0; r < 4; r++) acc[mt][nt][r] = 0.f;

    const int KT = K / BK;

    auto load_tile = [&](int buf, int k0) {
        #pragma unroll
        for (int u = 0; u < 4; u++) {
            int c   = tid + u * 256;       // 0..1023
            int row = c >> 3;
            int col = (c & 7) * 4;
            cp_async16(asmem + (uint32_t)((buf * BM * KST + row * KST + col) * 4),
                       A + (size_t)(bm + row) * K + k0 + col);
            cp_async16(bsmem + (uint32_t)((buf * BN * KST + row * KST + col) * 4),
                       W + (size_t)(bn + row) * K + k0 + col);
        }
        cp_commit();
    };

    load_tile(0, 0);

    for (int kt = 0; kt < KT; kt++) {
        int cur = kt & 1;
        if (kt + 1 < KT) {
            load_tile(cur ^ 1, (kt + 1) * BK);
            cp_wait<1>();
        } else {
            cp_wait<0>();
        }
        __syncthreads();

        const float* as = As + cur * BM * KST;
        const float* bs = Bs + cur * BN * KST;

        #pragma unroll
        for (int ks = 0; ks < BK; ks += 8) {
            uint32_t af[2][4], bf[8][2];
            #pragma unroll
            for (int mt = 0; mt < 2; mt++) {
                const float* ap = as + (wm + mt * 16 + lr) * KST + ks + lc;
                af[mt][0] = __float_as_uint(ap[0]);
                af[mt][1] = __float_as_uint(ap[8 * KST]);
                af[mt][2] = __float_as_uint(ap[4]);
                af[mt][3] = __float_as_uint(ap[8 * KST + 4]);
            }
            #pragma unroll
            for (int nt = 0; nt < 8; nt++) {
                const float* bp = bs + (wn + nt * 8 + lr) * KST + ks + lc;
                bf[nt][0] = __float_as_uint(bp[0]);
                bf[nt][1] = __float_as_uint(bp[4]);
            }
            #pragma unroll
            for (int mt = 0; mt < 2; mt++)
                #pragma unroll
                for (int nt = 0; nt < 8; nt++) {
                    asm volatile(
                        "mma.sync.aligned.m16n8k8.row.col.f32.tf32.tf32.f32 "
                        "{%0,%1,%2,%3}, {%4,%5,%6,%7}, {%8,%9}, {%0,%1,%2,%3};\n"
                        : "+f"(acc[mt][nt][0]), "+f"(acc[mt][nt][1]),
                          "+f"(acc[mt][nt][2]), "+f"(acc[mt][nt][3])
                        : "r"(af[mt][0]), "r"(af[mt][1]), "r"(af[mt][2]), "r"(af[mt][3]),
                          "r"(bf[nt][0]), "r"(bf[nt][1]));
                }
        }
        __syncthreads();
    }

    // epilogue
    #pragma unroll
    for (int mt = 0; mt < 2; mt++) {
        #pragma unroll
        for (int nt = 0; nt < 8; nt++) {
            int row = bm + wm + mt * 16 + lr;
            int col = bn + wn + nt * 8 + 2 * lc;
            float b0 = bias[col], b1 = bias[col + 1];
            #pragma unroll
            for (int h = 0; h < 2; h++) {
                int r = row + h * 8;
                float v0 = acc[mt][nt][2 * h + 0] + b0;
                float v1 = acc[mt][nt][2 * h + 1] + b1;
                if (mode == 1) {
                    v0 = to_tf32(0.5f * v0 * (1.f + erff(v0 * 0.70710678118654752f)));
                    v1 = to_tf32(0.5f * v1 * (1.f + erff(v1 * 0.70710678118654752f)));
                } else if (mode == 2) {
                    const float* ar = add + (size_t)r * N + col;
                    v0 += ar[0]; v1 += ar[1];
                }
                float2* outp = (float2*)(C + (size_t)r * N + col);
                *outp = make_float2(v0, v1);
            }
        }
    }
}

// ---------------------------------------------------------------------------
// Windowed attention: one block per (window, head). 64 threads (1 per query).
// Output tf32-rounded (feeds proj GEMM).
// ---------------------------------------------------------------------------
__global__ __launch_bounds__(64)
void attn_kernel(const float* __restrict__ q, const float* __restrict__ k,
                 const float* __restrict__ v, const float* __restrict__ btab,
                 float* __restrict__ ctx) {
    __shared__ float qs[64][32];
    __shared__ float ks[64][32];
    __shared__ float vs[64][32];
    __shared__ float sc[64][65];
    __shared__ int   rid[64];

    int win  = blockIdx.x;
    int head = blockIdx.y;
    int n    = threadIdx.x;

    int wi = win & 63;
    int wh = wi >> 3, ww = wi & 7;
    int i  = n  >> 3, j  = n  & 7;

    int hs = wh * 8 + i, wc = ww * 8 + j;
    int rh = (hs < 56) ? 0 : ((hs < 60) ? 1 : 2);
    int rw = (wc < 56) ? 0 : ((wc < 60) ? 1 : 2);
    rid[n] = rh * 3 + rw;

    size_t base = ((size_t)win * 64) * CDIM + head * HDIM;
    const float4* q4 = (const float4*)(q + base + (size_t)n * CDIM);
    const float4* k4 = (const float4*)(k + base + (size_t)n * CDIM);
    const float4* v4 = (const float4*)(v + base + (size_t)n * CDIM);
    #pragma unroll
    for (int u = 0; u < 8; u++) {
        ((float4*)qs[n])[u] = q4[u];
        ((float4*)ks[n])[u] = k4[u];
        ((float4*)vs[n])[u] = v4[u];
    }
    __syncthreads();

    float qr[32];
    #pragma unroll
    for (int d = 0; d < 32; d++) qr[d] = qs[n][d];

    const float scale = 0.17677669529663687f;
    int myrid = rid[n];

    for (int m = 0; m < 64; m++) {
        float acc = 0.f;
        #pragma unroll
        for (int d = 0; d < 32; d++) acc += qr[d] * ks[m][d];
        int hk = m >> 3, wk = m & 7;
        int bidx = (i - hk + 7) * 15 + (j - wk + 7);
        float bv = btab[bidx * NHEADS + head];
        float msk = (rid[m] == myrid) ? 0.f : -100.f;
        sc[n][m] = acc * scale + bv + msk;
    }

    float mx = -1e30f;
    for (int m = 0; m < 64; m++) mx = fmaxf(mx, sc[n][m]);
    float sum = 0.f;
    for (int m = 0; m < 64; m++) {
        float e = expf(sc[n][m] - mx);
        sc[n][m] = e;
        sum += e;
    }
    float accv[32];
    #pragma unroll
    for (int d = 0; d < 32; d++) accv[d] = 0.f;
    for (int m = 0; m < 64; m++) {
        float p = sc[n][m];
        #pragma unroll
        for (int d = 0; d < 32; d++) accv[d] += p * vs[m][d];
    }
    float inv = 1.f / sum;
    float* o = ctx + base + (size_t)n * CDIM;
    #pragma unroll
    for (int d = 0; d < 32; d++) o[d] = to_tf32(accv[d] * inv);
}

// ---------------------------------------------------------------------------
// launch
// ---------------------------------------------------------------------------
extern "C" void kernel_launch(void* const* d_in, const int* in_sizes, int n_in,
                              void* d_out, int out_size) {
    const float* hid    = (const float*)d_in[0];
    const float* q_w    = (const float*)d_in[1];
    const float* q_b    = (const float*)d_in[2];
    const float* k_w    = (const float*)d_in[3];
    const float* k_b    = (const float*)d_in[4];
    const float* v_w    = (const float*)d_in[5];
    const float* v_b    = (const float*)d_in[6];
    const float* proj_w = (const float*)d_in[7];
    const float* proj_b = (const float*)d_in[8];
    const float* relb   = (const float*)d_in[9];
    const float* ln1w   = (const float*)d_in[10];
    const float* ln1b   = (const float*)d_in[11];
    const float* ln2w   = (const float*)d_in[12];
    const float* ln2b   = (const float*)d_in[13];
    const float* fc1w   = (const float*)d_in[14];
    const float* fc1b   = (const float*)d_in[15];
    const float* fc2w   = (const float*)d_in[16];
    const float* fc2b   = (const float*)d_in[17];

    float* base = nullptr;
    cudaGetSymbolAddress((void**)&base, g_scratch);
    const size_t TC = (size_t)NTOK * CDIM;
    float* xw  = base + 0 * TC;
    float* qb  = base + 1 * TC;
    float* kb  = base + 2 * TC;
    float* vb  = base + 3 * TC;
    float* cx  = base + 4 * TC;
    float* po  = base + 5 * TC;
    float* hb  = base + 6 * TC;
    float* yb  = base + 7 * TC;
    float* mlp = base + 8 * TC;          // 4*TC
    float* wts = base + 12 * TC;         // tf32 weights
    float* wq  = wts;
    float* wk  = wq + (size_t)CDIM * CDIM;
    float* wv  = wk + (size_t)CDIM * CDIM;
    float* wp  = wv + (size_t)CDIM * CDIM;
    float* wf1 = wp + (size_t)CDIM * CDIM;
    float* wf2 = wf1 + (size_t)MLPD * CDIM;

    float* out = (float*)d_out;

    const int smem_bytes = 4 * BM * KST * sizeof(float);  // 73728
    cudaFuncSetAttribute(gemm_tf32_kernel,
                         cudaFuncAttributeMaxDynamicSharedMemorySize, smem_bytes);

    // 0. round weights to tf32
    const int CC = CDIM * CDIM, MC = MLPD * CDIM;
    round_tf32_kernel<<<(CC + 255) / 256, 256>>>(q_w, wq, CC);
    round_tf32_kernel<<<(CC + 255) / 256, 256>>>(k_w, wk, CC);
    round_tf32_kernel<<<(CC + 255) / 256, 256>>>(v_w, wv, CC);
    round_tf32_kernel<<<(CC + 255) / 256, 256>>>(proj_w, wp, CC);
    round_tf32_kernel<<<(MC + 255) / 256, 256>>>(fc1w, wf1, MC);
    round_tf32_kernel<<<(MC + 255) / 256, 256>>>(fc2w, wf2, MC);

    // 1. LN1 + shift + window partition (tf32 out)
    ln1_gather_kernel<<<NTOK, 128>>>(hid, ln1w, ln1b, xw);

    // 2. QKV projections
    dim3 gC(CDIM / 128, NTOK / 128);
    gemm_tf32_kernel<<<gC, 256, smem_bytes>>>(xw, wq, q_b, qb, CDIM, CDIM, 0, nullptr);
    gemm_tf32_kernel<<<gC, 256, smem_bytes>>>(xw, wk, k_b, kb, CDIM, CDIM, 0, nullptr);
    gemm_tf32_kernel<<<gC, 256, smem_bytes>>>(xw, wv, v_b, vb, CDIM, CDIM, 0, nullptr);

    // 3. windowed attention (tf32 out)
    attn_kernel<<<dim3(1024, NHEADS), 64>>>(qb, kb, vb, relb, cx);

    // 4. output projection
    gemm_tf32_kernel<<<gC, 256, smem_bytes>>>(cx, wp, proj_b, po, CDIM, CDIM, 0, nullptr);

    // 5. window reverse + unshift + residual
    resid_scatter_kernel<<<NTOK, 128>>>(hid, po, hb);

    // 6. LN2 (tf32 out)
    ln_plain_kernel<<<NTOK, 128>>>(hb, ln2w, ln2b, yb);

    // 7. fc1 + GELU (tf32 out)
    gemm_tf32_kernel<<<dim3(MLPD / 128, NTOK / 128), 256, smem_bytes>>>(
        yb, wf1, fc1b, mlp, MLPD, CDIM, 1, nullptr);

    // 8. fc2 + residual -> output
    gemm_tf32_kernel<<<gC, 256, smem_bytes>>>(mlp, wf2, fc2b, out, CDIM, MLPD, 2, hb);
}

// round 4
// speedup vs baseline: 4.0061x; 1.3098x over previous
#include <cuda_runtime.h>
#include <cuda_fp16.h>
#include <math.h>
#include <stdint.h>

// ---------------------------------------------------------------------------
// DonutSwinLayer: B=16, H=W=64, C=512, NH=16, HD=32, WS=8, N=64, SS=4, MLP=2048
// Round 4: fp16 mma.sync m16n8k16 GEMMs (fp32 accum), half activations,
//          fused QKV GEMM. (tcgen05 rejected by harness ptxas target.)
// ---------------------------------------------------------------------------

#define NTOK   65536
#define CDIM   512
#define NHEADS 16
#define HDIM   32
#define SSH    4
#define MLPD   2048
#define QKVN   1536

#define BM 128
#define BN 128
#define BK 32
#define KST 40          // padded row stride in halves (80B, conflict-free)
#define GEMM_SMEM (4 * 128 * KST * 2)   // 40960 B

__device__ unsigned char g_scratch[(size_t)28 * NTOK * CDIM + (1u << 24)];

// ============================ helpers ======================================
__device__ __forceinline__ void cp_async16(uint32_t s, const void* g) {
    asm volatile("cp.async.cg.shared.global [%0], [%1], 16;" :: "r"(s), "l"(g));
}
__device__ __forceinline__ void cp_commit() {
    asm volatile("cp.async.commit_group;");
}
template<int N_> __device__ __forceinline__ void cp_wait() {
    asm volatile("cp.async.wait_group %0;" :: "n"(N_));
}

__global__ void f2h_kernel(const float* __restrict__ src,
                           __half* __restrict__ dst, int n) {
    int i = (blockIdx.x * blockDim.x + threadIdx.x) * 4;
    if (i < n) {
        float4 v = *(const float4*)(src + i);
        __half2 a = __floats2half2_rn(v.x, v.y);
        __half2 b = __floats2half2_rn(v.z, v.w);
        *(__half2*)(dst + i)     = a;
        *(__half2*)(dst + i + 2) = b;
    }
}

__global__ void concat3_kernel(const float* __restrict__ a,
                               const float* __restrict__ b,
                               const float* __restrict__ c,
                               float* __restrict__ dst) {
    int i = blockIdx.x * blockDim.x + threadIdx.x;
    if (i < 512) dst[i] = a[i];
    else if (i < 1024) dst[i] = b[i - 512];
    else if (i < 1536) dst[i] = c[i - 1024];
}

__device__ __forceinline__ void block_reduce_2(float& s, float& s2) {
    #pragma unroll
    for (int o = 16; o > 0; o >>= 1) {
        s  += __shfl_down_sync(0xffffffffu, s,  o);
        s2 += __shfl_down_sync(0xffffffffu, s2, o);
    }
    __shared__ float sh[8];
    int w = threadIdx.x >> 5, l = threadIdx.x & 31;
    if (l == 0) { sh[w] = s; sh[4 + w] = s2; }
    __syncthreads();
    s  = sh[0] + sh[1] + sh[2] + sh[3];
    s2 = sh[4] + sh[5] + sh[6] + sh[7];
}

// ============================ LN kernels ===================================
// LN1 + cyclic shift + window partition, half output
__global__ void ln1_gather_kernel(const float* __restrict__ hid,
                                  const float* __restrict__ g,
                                  const float* __restrict__ b,
                                  __half* __restrict__ xw) {
    int wr = blockIdx.x;
    int t  = threadIdx.x;
    int b_  = wr >> 12;
    int rem = wr & 4095;
    int wi  = rem >> 6;
    int n   = rem & 63;
    int wh = wi >> 3, ww = wi & 7;
    int i  = n  >> 3, j  = n  & 7;
    int sh_ = ((wh * 8 + i) + SSH) & 63;
    int sw_ = ((ww * 8 + j) + SSH) & 63;
    const float* src = hid + ((size_t)b_ * 4096 + sh_ * 64 + sw_) * CDIM;

    float v[4];
    float s = 0.f, s2 = 0.f;
    #pragma unroll
    for (int u = 0; u < 4; u++) {
        v[u] = src[t + u * 128];
        s += v[u]; s2 += v[u] * v[u];
    }
    block_reduce_2(s, s2);
    float mu  = s * (1.f / CDIM);
    float var = s2 * (1.f / CDIM) - mu * mu;
    float inv = rsqrtf(var + 1e-5f);

    __half* dst = xw + (size_t)wr * CDIM;
    #pragma unroll
    for (int u = 0; u < 4; u++) {
        int c = t + u * 128;
        dst[c] = __float2half_rn((v[u] - mu) * inv * g[c] + b[c]);
    }
}

// plain LN, half output
__global__ void ln_plain_kernel(const float* __restrict__ x,
                                const float* __restrict__ g,
                                const float* __restrict__ b,
                                __half* __restrict__ y) {
    int r = blockIdx.x;
    int t = threadIdx.x;
    const float* src = x + (size_t)r * CDIM;
    float v[4];
    float s = 0.f, s2 = 0.f;
    #pragma unroll
    for (int u = 0; u < 4; u++) {
        v[u] = src[t + u * 128];
        s += v[u]; s2 += v[u] * v[u];
    }
    block_reduce_2(s, s2);
    float mu  = s * (1.f / CDIM);
    float var = s2 * (1.f / CDIM) - mu * mu;
    float inv = rsqrtf(var + 1e-5f);
    __half* dst = y + (size_t)r * CDIM;
    #pragma unroll
    for (int u = 0; u < 4; u++) {
        int c = t + u * 128;
        dst[c] = __float2half_rn((v[u] - mu) * inv * g[c] + b[c]);
    }
}

// window reverse + unshift + residual
__global__ void resid_scatter_kernel(const float* __restrict__ hid,
                                     const float* __restrict__ po,
                                     float* __restrict__ h) {
    int wr = blockIdx.x;
    int t  = threadIdx.x;
    int b_  = wr >> 12;
    int rem = wr & 4095;
    int wi  = rem >> 6;
    int n   = rem & 63;
    int wh = wi >> 3, ww = wi & 7;
    int i  = n  >> 3, j  = n  & 7;
    int sh_ = ((wh * 8 + i) + SSH) & 63;
    int sw_ = ((ww * 8 + j) + SSH) & 63;
    size_t dst  = ((size_t)b_ * 4096 + sh_ * 64 + sw_) * CDIM;
    size_t srcr = (size_t)wr * CDIM;
    #pragma unroll
    for (int u = 0; u < 4; u++) {
        int c = t + u * 128;
        h[dst + c] = hid[dst + c] + po[srcr + c];
    }
}

// ============================ fp16 GEMM ====================================
// C[m][n] = sum_k A[m][k]*W[n][k] + bias[n]
// A: M x K half, W: N x K half. 256 threads, 8 warps (4M x 2N), warp 32x64.
// mode: 0 half out, 1 gelu->half out, 2 float out + residual, 3 float out
__global__ __launch_bounds__(256)
void gemm_f16_kernel(const __half* __restrict__ A, const __half* __restrict__ W,
                     const float* __restrict__ bias, void* __restrict__ Cout,
                     int N, int K, int mode, const float* __restrict__ add) {
    extern __shared__ char smem[];
    uint32_t sb = (uint32_t)__cvta_generic_to_shared(smem);
    __half* sA = (__half*)smem;                    // [2][128][KST]
    __half* sB = (__half*)(smem + 2 * 128 * KST * 2);

    const int tid  = threadIdx.x;
    const int warp = tid >> 5;
    const int lane = tid & 31;
    const int bm   = blockIdx.y * BM;
    const int bn   = blockIdx.x * BN;
    const int wm   = (warp & 3) * 32;
    const int wn   = (warp >> 2) * 64;
    const int lr   = lane >> 2;   // 0..7
    const int lc   = lane & 3;    // 0..3

    float acc[2][8][4];
    #pragma unroll
    for (int mt = 0; mt < 2; mt++)
        #pragma unroll
        for (int nt = 0; nt < 8; nt++)
            #pragma unroll
            for (int r = 0; r < 4; r++) acc[mt][nt][r] = 0.f;

    const int KT = K / BK;

    // loader: tile = 128 rows x 32 halves = 512 16B-chunks per matrix,
    // 2 chunks/thread/matrix
    auto load_tile = [&](int buf, int k0) {
        uint32_t abase = sb + (uint32_t)(buf * 128 * KST * 2);
        uint32_t bbase = sb + (uint32_t)((2 * 128 * KST + buf * 128 * KST) * 2);
        #pragma unroll
        for (int u = 0; u < 2; u++) {
            int ch  = tid + u * 256;      // 0..511
            int row = ch >> 2;            // 0..127
            int kq  = ch & 3;             // 16B chunk within row
            uint32_t off = (uint32_t)(row * KST * 2 + kq * 16);
            cp_async16(abase + off, A + (size_t)(bm + row) * K + k0 + kq * 8);
            cp_async16(bbase + off, W + (size_t)(bn + row) * K + k0 + kq * 8);
        }
        cp_commit();
    };

    load_tile(0, 0);

    for (int kt = 0; kt < KT; kt++) {
        int cur = kt & 1;
        if (kt + 1 < KT) {
            load_tile(cur ^ 1, (kt + 1) * BK);
            cp_wait<1>();
        } else {
            cp_wait<0>();
        }
        __syncthreads();

        const __half* as = sA + cur * 128 * KST;
        const __half* bs = sB + cur * 128 * KST;

        #pragma unroll
        for (int ks = 0; ks < BK; ks += 16) {
            uint32_t af[2][4], bf[8][2];
            #pragma unroll
            for (int mt = 0; mt < 2; mt++) {
                const __half* ap = as + (wm + mt * 16 + lr) * KST + ks + 2 * lc;
                af[mt][0] = *(const uint32_t*)(ap);
                af[mt][1] = *(const uint32_t*)(ap + 8 * KST);
                af[mt][2] = *(const uint32_t*)(ap + 8);
                af[mt][3] = *(const uint32_t*)(ap + 8 * KST + 8);
            }
            #pragma unroll
            for (int nt = 0; nt < 8; nt++) {
                const __half* bp = bs + (wn + nt * 8 + lr) * KST + ks + 2 * lc;
                bf[nt][0] = *(const uint32_t*)(bp);
                bf[nt][1] = *(const uint32_t*)(bp + 8);
            }
            #pragma unroll
            for (int mt = 0; mt < 2; mt++)
                #pragma unroll
                for (int nt = 0; nt < 8; nt++) {
                    asm volatile(
                        "mma.sync.aligned.m16n8k16.row.col.f32.f16.f16.f32 "
                        "{%0,%1,%2,%3}, {%4,%5,%6,%7}, {%8,%9}, {%0,%1,%2,%3};\n"
                        : "+f"(acc[mt][nt][0]), "+f"(acc[mt][nt][1]),
                          "+f"(acc[mt][nt][2]), "+f"(acc[mt][nt][3])
                        : "r"(af[mt][0]), "r"(af[mt][1]), "r"(af[mt][2]), "r"(af[mt][3]),
                          "r"(bf[nt][0]), "r"(bf[nt][1]));
                }
        }
        __syncthreads();
    }

    // epilogue
    #pragma unroll
    for (int mt = 0; mt < 2; mt++) {
        #pragma unroll
        for (int nt = 0; nt < 8; nt++) {
            int col = bn + wn + nt * 8 + 2 * lc;
            float b0 = bias[col], b1 = bias[col + 1];
            #pragma unroll
            for (int h = 0; h < 2; h++) {
                int row = bm + wm + mt * 16 + lr + h * 8;
                float v0 = acc[mt][nt][2 * h + 0] + b0;
                float v1 = acc[mt][nt][2 * h + 1] + b1;
                if (mode == 1) {
                    v0 = 0.5f * v0 * (1.f + erff(v0 * 0.70710678118654752f));
                    v1 = 0.5f * v1 * (1.f + erff(v1 * 0.70710678118654752f));
                }
                if (mode <= 1) {
                    __half* crow = (__half*)Cout + (size_t)row * N + col;
                    *(__half2*)crow = __floats2half2_rn(v0, v1);
                } else {
                    if (mode == 2) {
                        const float* ar = add + (size_t)row * N + col;
                        v0 += ar[0]; v1 += ar[1];
                    }
                    float* crow = (float*)Cout + (size_t)row * N + col;
                    crow[0] = v0; crow[1] = v1;
                }
            }
        }
    }
}

// ============================ attention ====================================
// one block per (window, head), 64 threads (1 per query).
// q/k/v read from fused qkv buffer (row stride 1536), ctx written half.
__global__ __launch_bounds__(64)
void attn_kernel(const __half* __restrict__ qkv, const float* __restrict__ btab,
                 __half* __restrict__ ctx) {
    __shared__ float qs[64][32];
    __shared__ float ks[64][32];
    __shared__ float vs[64][33];
    __shared__ float sc[64][65];
    __shared__ int   rid[64];

    int win  = blockIdx.x;
    int head = blockIdx.y;
    int n    = threadIdx.x;

    int wi = win & 63;
    int wh = wi >> 3, ww = wi & 7;
    int i  = n  >> 3, j  = n  & 7;

    int hs = wh * 8 + i, wc = ww * 8 + j;
    int rh = (hs < 56) ? 0 : ((hs < 60) ? 1 : 2);
    int rw = (wc < 56) ? 0 : ((wc < 60) ? 1 : 2);
    rid[n] = rh * 3 + rw;

    size_t rowb = ((size_t)win * 64 + n) * QKVN;
    const __half2* qp = (const __half2*)(qkv + rowb + head * 32);
    const __half2* kp = (const __half2*)(qkv + rowb + 512 + head * 32);
    const __half2* vp = (const __half2*)(qkv + rowb + 1024 + head * 32);
    #pragma unroll
    for (int u = 0; u < 16; u++) {
        float2 a = __half22float2(qp[u]);
        float2 b = __half22float2(kp[u]);
        float2 c = __half22float2(vp[u]);
        qs[n][2 * u] = a.x; qs[n][2 * u + 1] = a.y;
        ks[n][2 * u] = b.x; ks[n][2 * u + 1] = b.y;
        vs[n][2 * u] = c.x; vs[n][2 * u + 1] = c.y;
    }
    __syncthreads();

    float qr[32];
    #pragma unroll
    for (int d = 0; d < 32; d++) qr[d] = qs[n][d];

    const float scale = 0.17677669529663687f;
    int myrid = rid[n];

    for (int m = 0; m < 64; m++) {
        float acc = 0.f;
        #pragma unroll
        for (int d = 0; d < 32; d++) acc += qr[d] * ks[m][d];
        int hk = m >> 3, wk = m & 7;
        int bidx = (i - hk + 7) * 15 + (j - wk + 7);
        float bv = btab[bidx * NHEADS + head];
        float msk = (rid[m] == myrid) ? 0.f : -100.f;
        sc[n][m] = acc * scale + bv + msk;
    }

    float mx = -1e30f;
    for (int m = 0; m < 64; m++) mx = fmaxf(mx, sc[n][m]);
    float sum = 0.f;
    for (int m = 0; m < 64; m++) {
        float e = expf(sc[n][m] - mx);
        sc[n][m] = e;
        sum += e;
    }
    float accv[32];
    #pragma unroll
    for (int d = 0; d < 32; d++) accv[d] = 0.f;
    for (int m = 0; m < 64; m++) {
        float p = sc[n][m];
        #pragma unroll
        for (int d = 0; d < 32; d++) accv[d] += p * vs[m][d];
    }
    float inv = 1.f / sum;
    __half* o = ctx + ((size_t)win * 64 + n) * CDIM + head * 32;
    #pragma unroll
    for (int d = 0; d < 32; d += 2)
        *(__half2*)(o + d) = __floats2half2_rn(accv[d] * inv, accv[d + 1] * inv);
}

// ============================ launch =======================================
extern "C" void kernel_launch(void* const* d_in, const int* in_sizes, int n_in,
                              void* d_out, int out_size) {
    const float* hid    = (const float*)d_in[0];
    const float* q_w    = (const float*)d_in[1];
    const float* q_b    = (const float*)d_in[2];
    const float* k_w    = (const float*)d_in[3];
    const float* k_b    = (const float*)d_in[4];
    const float* v_w    = (const float*)d_in[5];
    const float* v_b    = (const float*)d_in[6];
    const float* proj_w = (const float*)d_in[7];
    const float* proj_b = (const float*)d_in[8];
    const float* relb   = (const float*)d_in[9];
    const float* ln1w   = (const float*)d_in[10];
    const float* ln1b   = (const float*)d_in[11];
    const float* ln2w   = (const float*)d_in[12];
    const float* ln2b   = (const float*)d_in[13];
    const float* fc1w   = (const float*)d_in[14];
    const float* fc1b   = (const float*)d_in[15];
    const float* fc2w   = (const float*)d_in[16];
    const float* fc2b   = (const float*)d_in[17];

    unsigned char* base = nullptr;
    cudaGetSymbolAddress((void**)&base, g_scratch);
    const size_t TC = (size_t)NTOK * CDIM;
    __half* xw   = (__half*)base;                         // TC halves
    __half* qkvb = (__half*)(base + TC * 2);              // 3*TC halves
    __half* cx   = (__half*)(base + TC * 8);              // TC halves
    float*  po   = (float*)(base + TC * 10);              // TC floats
    float*  hb   = (float*)(base + TC * 14);              // TC floats
    __half* yb   = (__half*)(base + TC * 18);             // TC halves
    __half* mlp  = (__half*)(base + TC * 20);             // 4*TC halves
    unsigned char* wbase = base + TC * 28;
    const size_t CC = (size_t)CDIM * CDIM, MC = (size_t)MLPD * CDIM;
    __half* wqkv = (__half*)wbase;                        // 3*CC
    __half* wp   = wqkv + 3 * CC;
    __half* wf1  = wp + CC;
    __half* wf2  = wf1 + MC;
    float*  qkvbias = (float*)(wf2 + MC);

    float* out = (float*)d_out;

    // prepass: weights -> half, fused qkv weight+bias
    f2h_kernel<<<(int)(CC / 4 + 255) / 256, 256>>>(q_w, wqkv, (int)CC);
    f2h_kernel<<<(int)(CC / 4 + 255) / 256, 256>>>(k_w, wqkv + CC, (int)CC);
    f2h_kernel<<<(int)(CC / 4 + 255) / 256, 256>>>(v_w, wqkv + 2 * CC, (int)CC);
    f2h_kernel<<<(int)(CC / 4 + 255) / 256, 256>>>(proj_w, wp, (int)CC);
    f2h_kernel<<<(int)(MC / 4 + 255) / 256, 256>>>(fc1w, wf1, (int)MC);
    f2h_kernel<<<(int)(MC / 4 + 255) / 256, 256>>>(fc2w, wf2, (int)MC);
    concat3_kernel<<<6, 256>>>(q_b, k_b, v_b, qkvbias);

    // 1. LN1 + shift + window partition
    ln1_gather_kernel<<<NTOK, 128>>>(hid, ln1w, ln1b, xw);

    // 2. fused QKV projection (N=1536)
    gemm_f16_kernel<<<dim3(QKVN / BN, NTOK / BM), 256, GEMM_SMEM>>>(
        xw, wqkv, qkvbias, qkvb, QKVN, CDIM, 0, nullptr);

    // 3. windowed attention
    attn_kernel<<<dim3(1024, NHEADS), 64>>>(qkvb, relb, cx);

    // 4. output projection (float out)
    gemm_f16_kernel<<<dim3(CDIM / BN, NTOK / BM), 256, GEMM_SMEM>>>(
        cx, wp, proj_b, po, CDIM, CDIM, 3, nullptr);

    // 5. window reverse + unshift + residual
    resid_scatter_kernel<<<NTOK, 128>>>(hid, po, hb);

    // 6. LN2
    ln_plain_kernel<<<NTOK, 128>>>(hb, ln2w, ln2b, yb);

    // 7. fc1 + GELU (half out)
    gemm_f16_kernel<<<dim3(MLPD / BN, NTOK / BM), 256, GEMM_SMEM>>>(
        yb, wf1, fc1b, mlp, MLPD, CDIM, 1, nullptr);

    // 8. fc2 + residual -> fp32 output
    gemm_f16_kernel<<<dim3(CDIM / BN, NTOK / BM), 256, GEMM_SMEM>>>(
        mlp, wf2, fc2b, out, CDIM, MLPD, 2, hb);
}